// round 8
// baseline (speedup 1.0000x reference)
#include <cuda_runtime.h>
#include <cstdint>

#define T_STEPS   8192
#define HID       1024
#define GATES     4096
#define REC_GRID  128
#define FLAG_STRIDE 32   // 32 u32 = 128B: one flag per L2 line

// ---------------- scratch (static device globals; no allocations) ----------
__device__ float g_gates[(size_t)T_STEPS * GATES];   // 128 MB gate pre-activations
__device__ float g_hbuf[2][HID];                     // double-buffered hidden state
__device__ __align__(128) unsigned g_flags[REC_GRID * FLAG_STRIDE]; // strided flags
__device__ __align__(128) unsigned g_gen;            // broadcast generation word

// ---------------- strong-op primitives --------------------------------------
__device__ __forceinline__ void st_release_gpu(unsigned* p, unsigned v) {
    asm volatile("st.release.gpu.global.u32 [%0], %1;" :: "l"(p), "r"(v) : "memory");
}
__device__ __forceinline__ unsigned ld_acquire_gpu(const unsigned* p) {
    unsigned v;
    asm volatile("ld.acquire.gpu.global.u32 %0, [%1];" : "=r"(v) : "l"(p) : "memory");
    return v;
}
__device__ __forceinline__ void st_relaxed_gpu_f(float* p, float v) {
    asm volatile("st.relaxed.gpu.global.f32 [%0], %1;" :: "l"(p), "f"(v) : "memory");
}
// L2-coherent (weak) data load for the h / gates stream.
__device__ __forceinline__ float ldcg_f(const float* p) {
    float v; asm volatile("ld.global.cg.f32 %0, [%1];" : "=f"(v) : "l"(p)); return v;
}

// ======================= Kernel 1: gates_x GEMM =============================
// C[m,n] = sum_k x[m,k] * W_ih[n,k] + b_ih[n] + b_hh[n]
#define BM 128
#define BN 128
#define BK 8

__global__ __launch_bounds__(256) void gemm_gates_kernel(
    const float* __restrict__ x, const float* __restrict__ Wih,
    const float* __restrict__ b_ih, const float* __restrict__ b_hh)
{
    // Reset barrier state every replay (stream-ordered before the rec kernel).
    if (blockIdx.x == 0 && blockIdx.y == 0) {
        if (threadIdx.x < REC_GRID) g_flags[threadIdx.x * FLAG_STRIDE] = 0u;
        if (threadIdx.x == 0)       g_gen = 0u;
    }

    __shared__ float As[BK][BM + 4];
    __shared__ float Bs[BK][BN + 4];

    const int tid  = threadIdx.x;
    const int arow = tid >> 1;
    const int acol = (tid & 1) << 2;
    const int trow = tid >> 4;
    const int tcol = tid & 15;

    const float* xg = x   + (size_t)(blockIdx.y * BM + arow) * 1024 + acol;
    const float* wg = Wih + (size_t)(blockIdx.x * BN + arow) * 1024 + acol;

    float acc[8][8];
#pragma unroll
    for (int i = 0; i < 8; i++)
#pragma unroll
        for (int j = 0; j < 8; j++) acc[i][j] = 0.f;

    for (int k0 = 0; k0 < 1024; k0 += BK) {
        float4 av = *(const float4*)(xg + k0);
        float4 bv = *(const float4*)(wg + k0);
        As[acol + 0][arow] = av.x; As[acol + 1][arow] = av.y;
        As[acol + 2][arow] = av.z; As[acol + 3][arow] = av.w;
        Bs[acol + 0][arow] = bv.x; Bs[acol + 1][arow] = bv.y;
        Bs[acol + 2][arow] = bv.z; Bs[acol + 3][arow] = bv.w;
        __syncthreads();

#pragma unroll
        for (int k = 0; k < BK; k++) {
            float4 a0 = *(const float4*)&As[k][trow * 8];
            float4 a1 = *(const float4*)&As[k][trow * 8 + 4];
            float4 b0 = *(const float4*)&Bs[k][tcol * 8];
            float4 b1 = *(const float4*)&Bs[k][tcol * 8 + 4];
            float a[8] = {a0.x, a0.y, a0.z, a0.w, a1.x, a1.y, a1.z, a1.w};
            float b[8] = {b0.x, b0.y, b0.z, b0.w, b1.x, b1.y, b1.z, b1.w};
#pragma unroll
            for (int i = 0; i < 8; i++)
#pragma unroll
                for (int j = 0; j < 8; j++)
                    acc[i][j] = fmaf(a[i], b[j], acc[i][j]);
        }
        __syncthreads();
    }

    const int cbase = blockIdx.x * BN + tcol * 8;
    float bias[8];
#pragma unroll
    for (int j = 0; j < 8; j++) bias[j] = b_ih[cbase + j] + b_hh[cbase + j];

#pragma unroll
    for (int i = 0; i < 8; i++) {
        float* crow = g_gates + (size_t)(blockIdx.y * BM + trow * 8 + i) * GATES + cbase;
        float4 o0, o1;
        o0.x = acc[i][0] + bias[0]; o0.y = acc[i][1] + bias[1];
        o0.z = acc[i][2] + bias[2]; o0.w = acc[i][3] + bias[3];
        o1.x = acc[i][4] + bias[4]; o1.y = acc[i][5] + bias[5];
        o1.z = acc[i][6] + bias[6]; o1.w = acc[i][7] + bias[7];
        *(float4*)(crow)     = o0;
        *(float4*)(crow + 4) = o1;
    }
}

// ======================= Kernel 2: cooperative recurrence ===================
// ONE cooperative launch, 128 CTAs x 1024 threads. CTA b owns hidden units
// [8b,8b+8); its W_hh slice lives in registers for all 8192 steps.
// Step barrier (root-aggregated, store-based — no atomics, no bulk polling):
//   arrive:    each CTA's lane0 (warp0) st.release flag[b] = t+1   (parallel,
//              flags strided one L2 line apart)
//   aggregate: CTA0 warp0, lane l acquire-polls flags 4l..4l+3 (one CTA polls)
//   broadcast: CTA0 lane0 st.release g_gen = t+1; other CTAs' lane0
//              acquire-polls the single g_gen word
// R6 failed by all-CTAs-poll-all-flags; R7 by 128 serialized arrival RMWs.
__global__ __launch_bounds__(1024, 1) void lstm_rec_coop(
    const float* __restrict__ Whh, const float* __restrict__ h0,
    const float* __restrict__ c0, float* __restrict__ out)
{
    __shared__ float h_s[HID];
    __shared__ float part_s[32 * 33];
    __shared__ float red_s[32];
    __shared__ float gx_s[32];
    __shared__ float c_s[8];

    const int tid  = threadIdx.x;
    const int w    = tid >> 5;
    const int l    = tid & 31;
    const int b    = blockIdx.x;
    const int base = b * 8;
    const int R    = (l >> 3) * HID + base + (l & 7);   // this lane's gate row

    // Load W slice into registers (held for the entire sequence).
    float4 Wreg[8];
    {
        const float4* wrow = (const float4*)(Whh + (size_t)R * HID + w * 32);
#pragma unroll
        for (int k = 0; k < 8; k++) Wreg[k] = wrow[k];
    }

    if (tid < 8) c_s[tid] = c0[base + tid];   // cell state stays in SMEM

    for (int t = 0; t < T_STEPS; t++) {
        // ---- phase A: stage h + this step's gates_x slice ----
        const float* src = (t == 0) ? h0 : g_hbuf[t & 1];
        h_s[tid] = ldcg_f(src + tid);
        if (w == 0) gx_s[l] = ldcg_f(&g_gates[(size_t)t * GATES + R]);
        __syncthreads();

        // ---- phase B: 32x32 partial dot, 2 accumulators (shorter FMA chain) ----
        float acc0 = 0.f, acc1 = 0.f;
        const float4* hv = (const float4*)h_s + w * 8;
#pragma unroll
        for (int k = 0; k < 8; k += 2) {
            float4 h4a = hv[k];
            float4 h4b = hv[k + 1];
            acc0 = fmaf(Wreg[k].x, h4a.x, acc0);
            acc0 = fmaf(Wreg[k].y, h4a.y, acc0);
            acc0 = fmaf(Wreg[k].z, h4a.z, acc0);
            acc0 = fmaf(Wreg[k].w, h4a.w, acc0);
            acc1 = fmaf(Wreg[k + 1].x, h4b.x, acc1);
            acc1 = fmaf(Wreg[k + 1].y, h4b.y, acc1);
            acc1 = fmaf(Wreg[k + 1].z, h4b.z, acc1);
            acc1 = fmaf(Wreg[k + 1].w, h4b.w, acc1);
        }
        part_s[w * 33 + l] = acc0 + acc1;
        __syncthreads();

        // ---- phase C: transpose reduce: warp w sums local row w ----
        float v = part_s[l * 33 + w];
#pragma unroll
        for (int s = 16; s > 0; s >>= 1)
            v += __shfl_xor_sync(0xffffffffu, v, s);
        if (l == 0) red_s[w] = v + gx_s[w];
        __syncthreads();

        // ---- phase D+E: warp 0 does gate math, publish, and the barrier ----
        if (w == 0) {
            const unsigned want = (unsigned)(t + 1);
            if (l < 8) {
                float xi = red_s[l];
                float xf = red_s[8 + l];
                float xg = red_s[16 + l];
                float xo = red_s[24 + l];
                float ii = 1.f / (1.f + __expf(-xi));
                float ff = 1.f / (1.f + __expf(-xf));
                float gg = tanhf(xg);
                float oo = 1.f / (1.f + __expf(-xo));
                float c  = fmaf(ff, c_s[l], ii * gg);
                c_s[l]   = c;
                float h  = oo * tanhf(c);
                out[(size_t)t * HID + base + l] = h;
                st_relaxed_gpu_f(&g_hbuf[(t + 1) & 1][base + l], h);
            }
            __syncwarp();   // h stores (lanes 0-7) happen-before lane0's release
            if (t + 1 < T_STEPS) {
                if (l == 0)
                    st_release_gpu(&g_flags[b * FLAG_STRIDE], want);
                if (b == 0) {
                    // root: lane l acquire-polls flags 4l..4l+3 (parallel lines)
                    const unsigned* f = &g_flags[(l * 4) * FLAG_STRIDE];
                    for (;;) {
                        unsigned f0 = ld_acquire_gpu(f + 0 * FLAG_STRIDE);
                        unsigned f1 = ld_acquire_gpu(f + 1 * FLAG_STRIDE);
                        unsigned f2 = ld_acquire_gpu(f + 2 * FLAG_STRIDE);
                        unsigned f3 = ld_acquire_gpu(f + 3 * FLAG_STRIDE);
                        bool ok = f0 >= want && f1 >= want &&
                                  f2 >= want && f3 >= want;
                        if (__all_sync(0xffffffffu, ok)) break;
                    }
                    if (l == 0) st_release_gpu(&g_gen, want);
                } else {
                    if (l == 0)
                        while (ld_acquire_gpu(&g_gen) < want) { }
                }
            }
        }
        __syncthreads();   // fan the acquire out to the whole CTA
    }
}

// ======================= launch =============================================
extern "C" void kernel_launch(void* const* d_in, const int* in_sizes, int n_in,
                              void* d_out, int out_size)
{
    const float* x    = (const float*)d_in[0];
    const float* Wih  = (const float*)d_in[1];
    const float* Whh  = (const float*)d_in[2];
    const float* b_ih = (const float*)d_in[3];
    const float* b_hh = (const float*)d_in[4];
    const float* h0   = (const float*)d_in[5];
    const float* c0   = (const float*)d_in[6];
    float* out = (float*)d_out;

    dim3 ggrid(GATES / BN, T_STEPS / BM);
    gemm_gates_kernel<<<ggrid, 256>>>(x, Wih, b_ih, b_hh);

    void* args[4] = { (void*)&Whh, (void*)&h0, (void*)&c0, (void*)&out };
    cudaLaunchCooperativeKernel((void*)lstm_rec_coop,
                                dim3(REC_GRID, 1, 1), dim3(1024, 1, 1),
                                args, 0, (cudaStream_t)0);
}

// round 9
// speedup vs baseline: 1.8022x; 1.8022x over previous
#include <cuda_runtime.h>
#include <cstdint>

#define T_STEPS   8192
#define HID       1024
#define GATES     4096
#define REC_GRID  128
#define NCNT      32          // 32 arrival counters, 4 CTAs each
#define CNT_STRIDE 32         // 32 u32 = 128B: one counter per L2 line

// ---------------- scratch (static device globals; no allocations) ----------
__device__ float g_gates[(size_t)T_STEPS * GATES];   // 128 MB gate pre-activations
__device__ __align__(128) float g_hbuf[2][HID];      // double-buffered hidden state
__device__ __align__(128) unsigned g_cnt[NCNT * CNT_STRIDE];  // arrival counters

// ---------------- strong-op primitives --------------------------------------
__device__ __forceinline__ unsigned atom_add_release_gpu(unsigned* p, unsigned v) {
    unsigned old;
    asm volatile("atom.add.release.gpu.global.u32 %0, [%1], %2;"
                 : "=r"(old) : "l"(p), "r"(v) : "memory");
    return old;
}
__device__ __forceinline__ unsigned ld_acquire_gpu(const unsigned* p) {
    unsigned v;
    asm volatile("ld.acquire.gpu.global.u32 %0, [%1];" : "=r"(v) : "l"(p) : "memory");
    return v;
}
__device__ __forceinline__ void st_relaxed_gpu_f(float* p, float v) {
    asm volatile("st.relaxed.gpu.global.f32 [%0], %1;" :: "l"(p), "f"(v) : "memory");
}
// L2-coherent (weak) data load for the h / gates stream.
__device__ __forceinline__ float ldcg_f(const float* p) {
    float v; asm volatile("ld.global.cg.f32 %0, [%1];" : "=f"(v) : "l"(p)); return v;
}

// Fast, accuracy-safe nonlinearities (err ~1e-6 rel; budget 1e-3).
__device__ __forceinline__ float sigmoid_f(float x) {
    return __fdividef(1.f, 1.f + __expf(-x));
}
__device__ __forceinline__ float tanh_f(float x) {
    float xc = fminf(fmaxf(x, -15.f), 15.f);   // clamp: no inf from expf
    float e  = __expf(2.f * xc);
    return __fdividef(e - 1.f, e + 1.f);
}

// ======================= Kernel 1: gates_x GEMM =============================
// C[m,n] = sum_k x[m,k] * W_ih[n,k] + b_ih[n] + b_hh[n]
#define BM 128
#define BN 128
#define BK 8

__global__ __launch_bounds__(256) void gemm_gates_kernel(
    const float* __restrict__ x, const float* __restrict__ Wih,
    const float* __restrict__ b_ih, const float* __restrict__ b_hh)
{
    // Reset barrier counters every replay (stream-ordered before the rec kernel).
    if (blockIdx.x == 0 && blockIdx.y == 0 && threadIdx.x < NCNT)
        g_cnt[threadIdx.x * CNT_STRIDE] = 0u;

    __shared__ float As[BK][BM + 4];
    __shared__ float Bs[BK][BN + 4];

    const int tid  = threadIdx.x;
    const int arow = tid >> 1;
    const int acol = (tid & 1) << 2;
    const int trow = tid >> 4;
    const int tcol = tid & 15;

    const float* xg = x   + (size_t)(blockIdx.y * BM + arow) * 1024 + acol;
    const float* wg = Wih + (size_t)(blockIdx.x * BN + arow) * 1024 + acol;

    float acc[8][8];
#pragma unroll
    for (int i = 0; i < 8; i++)
#pragma unroll
        for (int j = 0; j < 8; j++) acc[i][j] = 0.f;

    for (int k0 = 0; k0 < 1024; k0 += BK) {
        float4 av = *(const float4*)(xg + k0);
        float4 bv = *(const float4*)(wg + k0);
        As[acol + 0][arow] = av.x; As[acol + 1][arow] = av.y;
        As[acol + 2][arow] = av.z; As[acol + 3][arow] = av.w;
        Bs[acol + 0][arow] = bv.x; Bs[acol + 1][arow] = bv.y;
        Bs[acol + 2][arow] = bv.z; Bs[acol + 3][arow] = bv.w;
        __syncthreads();

#pragma unroll
        for (int k = 0; k < BK; k++) {
            float4 a0 = *(const float4*)&As[k][trow * 8];
            float4 a1 = *(const float4*)&As[k][trow * 8 + 4];
            float4 b0 = *(const float4*)&Bs[k][tcol * 8];
            float4 b1 = *(const float4*)&Bs[k][tcol * 8 + 4];
            float a[8] = {a0.x, a0.y, a0.z, a0.w, a1.x, a1.y, a1.z, a1.w};
            float b[8] = {b0.x, b0.y, b0.z, b0.w, b1.x, b1.y, b1.z, b1.w};
#pragma unroll
            for (int i = 0; i < 8; i++)
#pragma unroll
                for (int j = 0; j < 8; j++)
                    acc[i][j] = fmaf(a[i], b[j], acc[i][j]);
        }
        __syncthreads();
    }

    const int cbase = blockIdx.x * BN + tcol * 8;
    float bias[8];
#pragma unroll
    for (int j = 0; j < 8; j++) bias[j] = b_ih[cbase + j] + b_hh[cbase + j];

#pragma unroll
    for (int i = 0; i < 8; i++) {
        float* crow = g_gates + (size_t)(blockIdx.y * BM + trow * 8 + i) * GATES + cbase;
        float4 o0, o1;
        o0.x = acc[i][0] + bias[0]; o0.y = acc[i][1] + bias[1];
        o0.z = acc[i][2] + bias[2]; o0.w = acc[i][3] + bias[3];
        o1.x = acc[i][4] + bias[4]; o1.y = acc[i][5] + bias[5];
        o1.z = acc[i][6] + bias[6]; o1.w = acc[i][7] + bias[7];
        *(float4*)(crow)     = o0;
        *(float4*)(crow + 4) = o1;
    }
}

// ======================= Kernel 2: cooperative recurrence ===================
// ONE cooperative launch, 128 CTAs x 1024 threads. CTA b owns hidden units
// [8b,8b+8); its W_hh slice lives in registers for all 8192 steps.
// Step barrier — built from the measured cost model of rounds 4/6/7/8:
//   * arrival serialization (grid.sync's 2.2us): fixed by 32 parallel
//     counters, 4 release-RMWs each (~128 cyc)
//   * poll contention (R7's +1us): fixed by nanosleep backoff
//   * extra hops (R8's +2us/hop): fixed by direct 32-lane poll, no root
__global__ __launch_bounds__(1024, 1) void lstm_rec_coop(
    const float* __restrict__ Whh, const float* __restrict__ h0,
    const float* __restrict__ c0, float* __restrict__ out)
{
    __shared__ float h_s[HID];
    __shared__ float part_s[32 * 33];
    __shared__ float red_s[32];
    __shared__ float gx_s[2][32];     // double-buffered, prefetched by warp 1

    const int tid  = threadIdx.x;
    const int w    = tid >> 5;
    const int l    = tid & 31;
    const int b    = blockIdx.x;
    const int base = b * 8;
    const int R    = (l >> 3) * HID + base + (l & 7);   // this lane's gate row

    // Load W slice into registers (held for the entire sequence).
    float4 Wreg[8];
    {
        const float4* wrow = (const float4*)(Whh + (size_t)R * HID + w * 32);
#pragma unroll
        for (int k = 0; k < 8; k++) Wreg[k] = wrow[k];
    }

    // Cell state lives in registers of warp 0, lanes 0-7.
    float c_reg = 0.f;
    if (w == 0 && l < 8) c_reg = c0[base + l];

    // Prime gx for step 0.
    if (w == 0) gx_s[0][l] = ldcg_f(&g_gates[(size_t)0 * GATES + R]);

    for (int t = 0; t < T_STEPS; t++) {
        // ---- phase A: stage h; warp 1 prefetches next step's gx ----
        const float* src = (t == 0) ? h0 : g_hbuf[t & 1];
        h_s[tid] = ldcg_f(src + tid);
        if (w == 1 && t + 1 < T_STEPS)
            gx_s[(t + 1) & 1][l] = ldcg_f(&g_gates[(size_t)(t + 1) * GATES + R]);
        __syncthreads();

        // ---- phase B: 32x32 partial dot, 2 accumulators ----
        float acc0 = 0.f, acc1 = 0.f;
        const float4* hv = (const float4*)h_s + w * 8;
#pragma unroll
        for (int k = 0; k < 8; k += 2) {
            float4 h4a = hv[k];
            float4 h4b = hv[k + 1];
            acc0 = fmaf(Wreg[k].x, h4a.x, acc0);
            acc0 = fmaf(Wreg[k].y, h4a.y, acc0);
            acc0 = fmaf(Wreg[k].z, h4a.z, acc0);
            acc0 = fmaf(Wreg[k].w, h4a.w, acc0);
            acc1 = fmaf(Wreg[k + 1].x, h4b.x, acc1);
            acc1 = fmaf(Wreg[k + 1].y, h4b.y, acc1);
            acc1 = fmaf(Wreg[k + 1].z, h4b.z, acc1);
            acc1 = fmaf(Wreg[k + 1].w, h4b.w, acc1);
        }
        part_s[w * 33 + l] = acc0 + acc1;
        __syncthreads();

        // ---- phase C: transpose reduce: warp w sums local row w ----
        float v = part_s[l * 33 + w];
#pragma unroll
        for (int s = 16; s > 0; s >>= 1)
            v += __shfl_xor_sync(0xffffffffu, v, s);
        if (l == 0) red_s[w] = v + gx_s[t & 1][w];
        __syncthreads();

        // ---- phase D+E: warp 0: parallel gate math, publish, barrier ----
        if (w == 0) {
            // 32 nonlinearities in parallel: lanes 0-7 i, 8-15 f, 16-23 g, 24-31 o
            float xg_ = red_s[l];
            float nl  = ((l >> 3) == 2) ? tanh_f(xg_) : sigmoid_f(xg_);
            int   j   = l & 7;
            float ii  = __shfl_sync(0xffffffffu, nl, j);
            float ff  = __shfl_sync(0xffffffffu, nl, j + 8);
            float gg  = __shfl_sync(0xffffffffu, nl, j + 16);
            float oo  = __shfl_sync(0xffffffffu, nl, j + 24);
            if (l < 8) {
                float c = fmaf(ff, c_reg, ii * gg);
                c_reg   = c;
                float h = oo * tanh_f(c);
                out[(size_t)t * HID + base + l] = h;
                st_relaxed_gpu_f(&g_hbuf[(t + 1) & 1][base + l], h);
            }
            __syncwarp();   // h stores happen-before lane0's release arrival

            if (t + 1 < T_STEPS) {
                const unsigned target = 4u * (unsigned)(t + 1);
                if (l == 0)
                    atom_add_release_gpu(&g_cnt[(b & 31) * CNT_STRIDE], 1u);
                // 32-lane direct poll of all 32 counters, nanosleep backoff
                int slept = 0;
                for (;;) {
                    unsigned cv = ld_acquire_gpu(&g_cnt[l * CNT_STRIDE]);
                    if (__all_sync(0xffffffffu, cv >= target)) break;
                    if (slept) __nanosleep(64);
                    slept = 1;
                }
            }
        }
        __syncthreads();   // fan the acquire out to the whole CTA
    }
}

// ======================= launch =============================================
extern "C" void kernel_launch(void* const* d_in, const int* in_sizes, int n_in,
                              void* d_out, int out_size)
{
    const float* x    = (const float*)d_in[0];
    const float* Wih  = (const float*)d_in[1];
    const float* Whh  = (const float*)d_in[2];
    const float* b_ih = (const float*)d_in[3];
    const float* b_hh = (const float*)d_in[4];
    const float* h0   = (const float*)d_in[5];
    const float* c0   = (const float*)d_in[6];
    float* out = (float*)d_out;

    dim3 ggrid(GATES / BN, T_STEPS / BM);
    gemm_gates_kernel<<<ggrid, 256>>>(x, Wih, b_ih, b_hh);

    void* args[4] = { (void*)&Whh, (void*)&h0, (void*)&c0, (void*)&out };
    cudaLaunchCooperativeKernel((void*)lstm_rec_coop,
                                dim3(REC_GRID, 1, 1), dim3(1024, 1, 1),
                                args, 0, (cudaStream_t)0);
}

// round 10
// speedup vs baseline: 1.8460x; 1.0243x over previous
#include <cuda_runtime.h>
#include <cooperative_groups.h>
#include <cstdint>

namespace cg = cooperative_groups;

#define T_STEPS   8192
#define HID       1024
#define GATES     4096
#define REC_GRID  128

// ---------------- scratch (static device globals; no allocations) ----------
__device__ float g_gates[(size_t)T_STEPS * GATES];   // 128 MB gate pre-activations
__device__ __align__(128) float g_hbuf[2][HID];      // double-buffered hidden state

// L2-coherent (weak) data load for the h / gates stream (grid.sync fences all).
__device__ __forceinline__ float ldcg_f(const float* p) {
    float v; asm volatile("ld.global.cg.f32 %0, [%1];" : "=f"(v) : "l"(p)); return v;
}

// Fast, accuracy-safe nonlinearities (rel err ~1e-6; budget 1e-3; validated R9).
__device__ __forceinline__ float sigmoid_f(float x) {
    return __fdividef(1.f, 1.f + __expf(-x));
}
__device__ __forceinline__ float tanh_f(float x) {
    float xc = fminf(fmaxf(x, -15.f), 15.f);   // clamp: no inf from expf
    float e  = __expf(2.f * xc);
    return __fdividef(e - 1.f, e + 1.f);
}

// ======================= Kernel 1: gates_x GEMM =============================
// C[m,n] = sum_k x[m,k] * W_ih[n,k] + b_ih[n] + b_hh[n]
#define BM 128
#define BN 128
#define BK 8

__global__ __launch_bounds__(256) void gemm_gates_kernel(
    const float* __restrict__ x, const float* __restrict__ Wih,
    const float* __restrict__ b_ih, const float* __restrict__ b_hh)
{
    __shared__ float As[BK][BM + 4];
    __shared__ float Bs[BK][BN + 4];

    const int tid  = threadIdx.x;
    const int arow = tid >> 1;
    const int acol = (tid & 1) << 2;
    const int trow = tid >> 4;
    const int tcol = tid & 15;

    const float* xg = x   + (size_t)(blockIdx.y * BM + arow) * 1024 + acol;
    const float* wg = Wih + (size_t)(blockIdx.x * BN + arow) * 1024 + acol;

    float acc[8][8];
#pragma unroll
    for (int i = 0; i < 8; i++)
#pragma unroll
        for (int j = 0; j < 8; j++) acc[i][j] = 0.f;

    for (int k0 = 0; k0 < 1024; k0 += BK) {
        float4 av = *(const float4*)(xg + k0);
        float4 bv = *(const float4*)(wg + k0);
        As[acol + 0][arow] = av.x; As[acol + 1][arow] = av.y;
        As[acol + 2][arow] = av.z; As[acol + 3][arow] = av.w;
        Bs[acol + 0][arow] = bv.x; Bs[acol + 1][arow] = bv.y;
        Bs[acol + 2][arow] = bv.z; Bs[acol + 3][arow] = bv.w;
        __syncthreads();

#pragma unroll
        for (int k = 0; k < BK; k++) {
            float4 a0 = *(const float4*)&As[k][trow * 8];
            float4 a1 = *(const float4*)&As[k][trow * 8 + 4];
            float4 b0 = *(const float4*)&Bs[k][tcol * 8];
            float4 b1 = *(const float4*)&Bs[k][tcol * 8 + 4];
            float a[8] = {a0.x, a0.y, a0.z, a0.w, a1.x, a1.y, a1.z, a1.w};
            float b[8] = {b0.x, b0.y, b0.z, b0.w, b1.x, b1.y, b1.z, b1.w};
#pragma unroll
            for (int i = 0; i < 8; i++)
#pragma unroll
                for (int j = 0; j < 8; j++)
                    acc[i][j] = fmaf(a[i], b[j], acc[i][j]);
        }
        __syncthreads();
    }

    const int cbase = blockIdx.x * BN + tcol * 8;
    float bias[8];
#pragma unroll
    for (int j = 0; j < 8; j++) bias[j] = b_ih[cbase + j] + b_hh[cbase + j];

#pragma unroll
    for (int i = 0; i < 8; i++) {
        float* crow = g_gates + (size_t)(blockIdx.y * BM + trow * 8 + i) * GATES + cbase;
        float4 o0, o1;
        o0.x = acc[i][0] + bias[0]; o0.y = acc[i][1] + bias[1];
        o0.z = acc[i][2] + bias[2]; o0.w = acc[i][3] + bias[3];
        o1.x = acc[i][4] + bias[4]; o1.y = acc[i][5] + bias[5];
        o1.z = acc[i][6] + bias[6]; o1.w = acc[i][7] + bias[7];
        *(float4*)(crow)     = o0;
        *(float4*)(crow + 4) = o1;
    }
}

// ======================= Kernel 2: cooperative recurrence ===================
// ONE cooperative launch, 128 CTAs x 1024 threads. CTA b owns hidden units
// [8b,8b+8); its W_hh slice lives in registers for all 8192 steps.
// Barrier: grid.sync() — measured best of 6 designs (2.1us/step floor set by
// visibility latency + slowest-of-128 straggler tax, not by arrival cost).
// Compute path carries R9's validated improvements: parallel 32-lane gate
// nonlinearities, warp-1 gx prefetch, c-state in registers, dual accumulators.
__global__ __launch_bounds__(1024, 1) void lstm_rec_coop(
    const float* __restrict__ Whh, const float* __restrict__ h0,
    const float* __restrict__ c0, float* __restrict__ out)
{
    cg::grid_group grid = cg::this_grid();

    __shared__ float h_s[HID];
    __shared__ float part_s[32 * 33];
    __shared__ float red_s[32];
    __shared__ float gx_s[2][32];     // double-buffered, prefetched by warp 1

    const int tid  = threadIdx.x;
    const int w    = tid >> 5;
    const int l    = tid & 31;
    const int b    = blockIdx.x;
    const int base = b * 8;
    const int R    = (l >> 3) * HID + base + (l & 7);   // this lane's gate row

    // Load W slice into registers (held for the entire sequence).
    float4 Wreg[8];
    {
        const float4* wrow = (const float4*)(Whh + (size_t)R * HID + w * 32);
#pragma unroll
        for (int k = 0; k < 8; k++) Wreg[k] = wrow[k];
    }

    // Cell state lives in registers of warp 0, lanes 0-7.
    float c_reg = 0.f;
    if (w == 0 && l < 8) c_reg = c0[base + l];

    // Prime gx for step 0.
    if (w == 0) gx_s[0][l] = ldcg_f(&g_gates[(size_t)0 * GATES + R]);

    for (int t = 0; t < T_STEPS; t++) {
        // ---- phase A: stage h; warp 1 prefetches next step's gx ----
        const float* src = (t == 0) ? h0 : g_hbuf[t & 1];
        h_s[tid] = ldcg_f(src + tid);
        if (w == 1 && t + 1 < T_STEPS)
            gx_s[(t + 1) & 1][l] = ldcg_f(&g_gates[(size_t)(t + 1) * GATES + R]);
        __syncthreads();

        // ---- phase B: 32x32 partial dot, 2 accumulators ----
        float acc0 = 0.f, acc1 = 0.f;
        const float4* hv = (const float4*)h_s + w * 8;
#pragma unroll
        for (int k = 0; k < 8; k += 2) {
            float4 h4a = hv[k];
            float4 h4b = hv[k + 1];
            acc0 = fmaf(Wreg[k].x, h4a.x, acc0);
            acc0 = fmaf(Wreg[k].y, h4a.y, acc0);
            acc0 = fmaf(Wreg[k].z, h4a.z, acc0);
            acc0 = fmaf(Wreg[k].w, h4a.w, acc0);
            acc1 = fmaf(Wreg[k + 1].x, h4b.x, acc1);
            acc1 = fmaf(Wreg[k + 1].y, h4b.y, acc1);
            acc1 = fmaf(Wreg[k + 1].z, h4b.z, acc1);
            acc1 = fmaf(Wreg[k + 1].w, h4b.w, acc1);
        }
        part_s[w * 33 + l] = acc0 + acc1;
        __syncthreads();

        // ---- phase C: transpose reduce: warp w sums local row w ----
        float v = part_s[l * 33 + w];
#pragma unroll
        for (int s = 16; s > 0; s >>= 1)
            v += __shfl_xor_sync(0xffffffffu, v, s);
        if (l == 0) red_s[w] = v + gx_s[t & 1][w];
        __syncthreads();

        // ---- phase D: warp 0: 32 parallel nonlinearities + c/h update ----
        if (w == 0) {
            float xg_ = red_s[l];
            float nl  = ((l >> 3) == 2) ? tanh_f(xg_) : sigmoid_f(xg_);
            int   j   = l & 7;
            float ii  = __shfl_sync(0xffffffffu, nl, j);
            float ff  = __shfl_sync(0xffffffffu, nl, j + 8);
            float gg  = __shfl_sync(0xffffffffu, nl, j + 16);
            float oo  = __shfl_sync(0xffffffffu, nl, j + 24);
            if (l < 8) {
                float c = fmaf(ff, c_reg, ii * gg);
                c_reg   = c;
                float h = oo * tanh_f(c);
                out[(size_t)t * HID + base + l] = h;
                g_hbuf[(t + 1) & 1][base + l]   = h;
            }
        }

        // ---- phase E: device-wide barrier (fences the h double-buffer) ----
        grid.sync();
    }
}

// ======================= launch =============================================
extern "C" void kernel_launch(void* const* d_in, const int* in_sizes, int n_in,
                              void* d_out, int out_size)
{
    const float* x    = (const float*)d_in[0];
    const float* Wih  = (const float*)d_in[1];
    const float* Whh  = (const float*)d_in[2];
    const float* b_ih = (const float*)d_in[3];
    const float* b_hh = (const float*)d_in[4];
    const float* h0   = (const float*)d_in[5];
    const float* c0   = (const float*)d_in[6];
    float* out = (float*)d_out;

    dim3 ggrid(GATES / BN, T_STEPS / BM);
    gemm_gates_kernel<<<ggrid, 256>>>(x, Wih, b_ih, b_hh);

    void* args[4] = { (void*)&Whh, (void*)&h0, (void*)&c0, (void*)&out };
    cudaLaunchCooperativeKernel((void*)lstm_rec_coop,
                                dim3(REC_GRID, 1, 1), dim3(1024, 1, 1),
                                args, 0, (cudaStream_t)0);
}